// round 14
// baseline (speedup 1.0000x reference)
#include <cuda_runtime.h>
#include <math.h>

#define NB 4
#define C_ 256
#define H_ 64
#define W_ 64
#define G_ 8
#define CG_ 32
#define P_ 9
#define HW_ (H_*W_)
#define M_ (C_*H_*W_)

// scratch (device globals; no allocation allowed)
__device__ float g_x1[NB*HW_*C_];          // NHWC conv+bias result
__device__ float g_xn[NB*HW_*C_];          // NHWC original x
__device__ float g_part[NB*1024*2];        // per-block partial sums
__device__ float g_ms[NB*2];               // per-sample mean, rstd

// fast exact-enough GELU: tanh-form with MUFU.TANH
__device__ __forceinline__ float gelu_fast(float v) {
    float u = 0.7978845608028654f * v * fmaf(0.044715f, v * v, 1.0f);
    float t;
    asm("tanh.approx.f32 %0, %1;" : "=f"(t) : "f"(u));
    return 0.5f * v * (1.0f + t);
}

// ---- f32x2 packed helpers (FFMA2 — only reachable via PTX) ----
typedef unsigned long long ull;
__device__ __forceinline__ ull dup2(float v) {
    ull r; asm("mov.b64 %0, {%1, %1};" : "=l"(r) : "f"(v)); return r;
}
__device__ __forceinline__ void fma2(ull& d, ull a, ull b) {
    asm("fma.rn.f32x2 %0, %1, %2, %0;" : "+l"(d) : "l"(a), "l"(b));
}
__device__ __forceinline__ float2 unpack2(ull v) {
    float2 f; asm("mov.b64 {%0, %1}, %2;" : "=f"(f.x), "=f"(f.y) : "l"(v)); return f;
}

// ---------------------------------------------------------------------------
// K1: depthwise 3x3 conv (+bias) NCHW -> NHWC, transpose x -> NHWC,
//     per-block partial GroupNorm sums. (R12 version — smem staging regressed.)
// grid: (W/32, C/32, N*H), block: (32, 8)
// ---------------------------------------------------------------------------
__global__ __launch_bounds__(256) void k_conv(const float* __restrict__ x,
                                              const float* __restrict__ dww,
                                              const float* __restrict__ dwb) {
    int wt = blockIdx.x, ct = blockIdx.y, nh = blockIdx.z;
    int n = nh >> 6, h = nh & 63;
    int w = wt * 32 + threadIdx.x;
    int c0 = ct * 32;

    __shared__ float t1[32][33];
    __shared__ float t0[32][33];
    __shared__ float rs8[8], rq8[8];

    float s1 = 0.f, s2 = 0.f;

    #pragma unroll
    for (int i = 0; i < 4; i++) {
        int cl = threadIdx.y * 4 + i;
        int c = c0 + cl;
        const float* xp = x + ((size_t)(n * C_ + c) * H_) * W_;
        float wgt[9];
        #pragma unroll
        for (int k = 0; k < 9; k++) wgt[k] = dww[c * 9 + k];
        float acc = dwb[c];
        float center = 0.f;
        #pragma unroll
        for (int dy = 0; dy < 3; dy++) {
            int hy = h + dy - 1;
            if (hy < 0 || hy >= H_) continue;
            #pragma unroll
            for (int dx = 0; dx < 3; dx++) {
                int wx = w + dx - 1;
                if (wx < 0 || wx >= W_) continue;
                float v = __ldg(xp + hy * W_ + wx);
                acc = fmaf(wgt[dy * 3 + dx], v, acc);
                if (dy == 1 && dx == 1) center = v;
            }
        }
        t1[cl][threadIdx.x] = acc;
        t0[cl][threadIdx.x] = center;
        s1 += acc;
        s2 += acc * acc;
    }

    #pragma unroll
    for (int o = 16; o; o >>= 1) {
        s1 += __shfl_xor_sync(0xFFFFFFFFu, s1, o);
        s2 += __shfl_xor_sync(0xFFFFFFFFu, s2, o);
    }
    if (threadIdx.x == 0) { rs8[threadIdx.y] = s1; rq8[threadIdx.y] = s2; }
    __syncthreads();
    if (threadIdx.x == 0 && threadIdx.y == 0) {
        float a = 0.f, b = 0.f;
        #pragma unroll
        for (int i = 0; i < 8; i++) { a += rs8[i]; b += rq8[i]; }
        int pid = (h * 2 + wt) * 8 + ct;
        g_part[(n * 1024 + pid) * 2 + 0] = a;
        g_part[(n * 1024 + pid) * 2 + 1] = b;
    }

    #pragma unroll
    for (int i = 0; i < 4; i++) {
        int ww = threadIdx.y + 8 * i;
        size_t pix = (size_t)(n * H_ + h) * W_ + wt * 32 + ww;
        g_x1[pix * C_ + c0 + threadIdx.x] = t1[threadIdx.x][ww];
        g_xn[pix * C_ + c0 + threadIdx.x] = t0[threadIdx.x][ww];
    }
}

// ---------------------------------------------------------------------------
// K2: finalize per-sample mean / rstd
// ---------------------------------------------------------------------------
__global__ void k_stats() {
    int n = blockIdx.x;
    int t = threadIdx.x;
    float s1 = 0.f, s2 = 0.f;
    for (int i = t; i < 1024; i += 256) {
        s1 += g_part[(n * 1024 + i) * 2 + 0];
        s2 += g_part[(n * 1024 + i) * 2 + 1];
    }
    __shared__ float rs[256];
    __shared__ float rq[256];
    rs[t] = s1; rq[t] = s2;
    __syncthreads();
    #pragma unroll
    for (int s = 128; s > 0; s >>= 1) {
        if (t < s) { rs[t] += rs[t + s]; rq[t] += rq[t + s]; }
        __syncthreads();
    }
    if (t == 0) {
        float mu = rs[0] / (float)M_;
        float var = rq[0] / (float)M_ - mu * mu;
        g_ms[n * 2 + 0] = mu;
        g_ms[n * 2 + 1] = rsqrtf(var + 1e-5f);
    }
}

// ---------------------------------------------------------------------------
// K3 (merged): GN + GELU + projection GEMM (FFMA2, pixel-packed) + softmax +
// weight precompute (to SMEM) + quad-pixel LDG.128 gather + coalesced store.
// smem layout (words):
//   [0,     9216)  Ys[256][36]  -> reused as w4 float4[72][32]
//   [9216, 16344)  O[216][33]   -> reused as Obuf[16][257] per half
//   [16344,18648)  wi int[72][32]
// 74.6KB -> 3 blocks/SM. grid (2,64,4), block 256.
// Gather/store phase uses only intra-warp data -> __syncwarp, warps drift.
// ---------------------------------------------------------------------------
#define YS_W   9216
#define O_W    7128
#define WI_W   2304
#define SMEM_MAIN ((YS_W + O_W + WI_W) * 4)

__global__ __launch_bounds__(256, 3) void k_main(const float* __restrict__ gng,
                                                 const float* __restrict__ gnb,
                                                 const float* __restrict__ offw,
                                                 const float* __restrict__ offb,
                                                 const float* __restrict__ maskw,
                                                 const float* __restrict__ maskb,
                                                 float* __restrict__ out) {
    extern __shared__ __align__(16) float sm[];
    float*  Ys   = sm;                         // [256][36]
    float*  O    = sm + YS_W;                  // [216][33]
    float4* w4s  = (float4*)sm;                // [72][32] float4 (overlays Ys)
    int*    wis  = (int*)(sm + YS_W + O_W);    // [72][32]
    float*  Obuf = sm + YS_W;                  // [16][257]  (overlays O)

    int wt = blockIdx.x, h = blockIdx.y, n = blockIdx.z;
    int w0 = wt * 32;
    int t = threadIdx.x;
    int lane = t & 31;
    int wid = t >> 5;

    float mu = g_ms[n * 2 + 0];
    float rstd = g_ms[n * 2 + 1];

    // ---- Phase A: GN + GELU into Ys[c][pix] ----
    size_t pixbase = (size_t)(n * H_ + h) * W_ + w0;
    #pragma unroll
    for (int q = 0; q < 4; q++) {
        int pix = wid * 4 + q;
        const float* src = g_x1 + (pixbase + pix) * C_;
        #pragma unroll
        for (int half = 0; half < 2; half++) {
            int c = lane * 4 + half * 128;
            float4 v  = *(const float4*)(src + c);
            float4 gg = *(const float4*)(gng + c);
            float4 bb = *(const float4*)(gnb + c);
            Ys[(c + 0) * 36 + pix] = gelu_fast(fmaf((v.x - mu) * rstd, gg.x, bb.x));
            Ys[(c + 1) * 36 + pix] = gelu_fast(fmaf((v.y - mu) * rstd, gg.y, bb.y));
            Ys[(c + 2) * 36 + pix] = gelu_fast(fmaf((v.z - mu) * rstd, gg.z, bb.z));
            Ys[(c + 3) * 36 + pix] = gelu_fast(fmaf((v.w - mu) * rstd, gg.w, bb.w));
        }
    }
    __syncthreads();

    // ---- Phase B: GEMM O[216][32] = W^T @ Ys + bias (f32x2 pixel pairs) ----
    if (t < 216) {
        int jt = t >> 2, pt = t & 3;
        int j0 = jt * 4;
        const float* wb;
        const float* bptr;
        int stride;
        if (j0 < 144) { wb = offw + j0; bptr = offb + j0; stride = 144; }
        else          { wb = maskw + (j0 - 144); bptr = maskb + (j0 - 144); stride = 72; }

        ull acc[16];   // [jj][pixpair]
        #pragma unroll
        for (int jj = 0; jj < 4; jj++) {
            ull b = dup2(bptr[jj]);
            #pragma unroll
            for (int pp = 0; pp < 4; pp++) acc[jj * 4 + pp] = b;
        }

        const ulonglong2* yc = (const ulonglong2*)(Ys + pt * 8);
        #pragma unroll 2
        for (int c = 0; c < 256; c++) {
            float4 wv = *(const float4*)(wb + (size_t)c * stride);
            ull wd[4];
            wd[0] = dup2(wv.x); wd[1] = dup2(wv.y); wd[2] = dup2(wv.z); wd[3] = dup2(wv.w);
            ulonglong2 ya = yc[0];
            ulonglong2 yb = yc[1];
            ull y0 = ya.x, y1 = ya.y, y2 = yb.x, y3 = yb.y;
            #pragma unroll
            for (int jj = 0; jj < 4; jj++) {
                fma2(acc[jj * 4 + 0], wd[jj], y0);
                fma2(acc[jj * 4 + 1], wd[jj], y1);
                fma2(acc[jj * 4 + 2], wd[jj], y2);
                fma2(acc[jj * 4 + 3], wd[jj], y3);
            }
            yc += 9;   // 36 floats = 9 ulonglong2
        }

        #pragma unroll
        for (int jj = 0; jj < 4; jj++)
            #pragma unroll
            for (int pp = 0; pp < 4; pp++) {
                float2 f = unpack2(acc[jj * 4 + pp]);
                O[(j0 + jj) * 33 + pt * 8 + 2 * pp + 0] = f.x;
                O[(j0 + jj) * 33 + pt * 8 + 2 * pp + 1] = f.y;
            }
    }
    __syncthreads();

    // ---- Phase C1: softmax + premultiplied bilinear weights -> SMEM ----
    {
        int g = wid, pix = lane;
        float ml[9];
        float mx = -1e30f;
        #pragma unroll
        for (int p = 0; p < P_; p++) {
            ml[p] = O[(144 + g * P_ + p) * 33 + pix];
            mx = fmaxf(mx, ml[p]);
        }
        float s = 0.f;
        #pragma unroll
        for (int p = 0; p < P_; p++) { ml[p] = __expf(ml[p] - mx); s += ml[p]; }
        float inv = 1.f / s;

        float wpixf = (float)(w0 + pix);
        float hf = (float)h;
        #pragma unroll
        for (int p = 0; p < P_; p++) {
            float ox = O[((g * P_ + p) * 2 + 0) * 33 + pix];
            float oy = O[((g * P_ + p) * 2 + 1) * 33 + pix];
            float fx = wpixf + (float)(p / 3 - 1) + ox;
            float fy = hf    + (float)(p % 3 - 1) + oy;
            fx = fminf(fmaxf(fx, -2.f), (float)(W_ + 1));
            fy = fminf(fmaxf(fy, -2.f), (float)(H_ + 1));
            float x0f = floorf(fx), y0f = floorf(fy);
            float wxf = fx - x0f, wyf = fy - y0f;
            int ix = (int)x0f, iy = (int)y0f;
            float m = ml[p] * inv;
            float ax0 = (ix >= 0 && ix < W_)          ? (1.f - wxf) : 0.f;
            float ax1 = (ix + 1 >= 0 && ix + 1 < W_)  ? wxf         : 0.f;
            float ay0 = (iy >= 0 && iy < H_)          ? (1.f - wyf) : 0.f;
            float ay1 = (iy + 1 >= 0 && iy + 1 < H_)  ? wyf         : 0.f;
            float4 wv;
            wv.x = m * ay0 * ax0;
            wv.y = m * ay0 * ax1;
            wv.z = m * ay1 * ax0;
            wv.w = m * ay1 * ax1;
            int ix0c = min(max(ix, 0), W_ - 1);
            int iy0c = min(max(iy, 0), H_ - 1);
            int dx   = min(max(ix + 1, 0), W_ - 1) - ix0c;
            int dy   = min(max(iy + 1, 0), H_ - 1) - iy0c;
            int off  = iy0c * W_ + ix0c;
            int idx = (g * P_ + p) * 32 + pix;
            w4s[idx] = wv;
            wis[idx] = off | (dx << 12) | (dy << 13);
        }
    }
    __syncthreads();   // Obuf overlays O; all warps' C1 reads of O must finish

    // ---- Phase C2+D: quad-pixel LDG.128 gather, two 16-pixel halves ----
    // All smem traffic below is intra-warp (warp g owns channels g*32..+31,
    // its own w4s/wis records, its own Obuf columns) -> __syncwarp only.
    {
        int g = wid;
        int pixsub = lane >> 3;
        int cq = lane & 7;
        const ulonglong2* xb =
            (const ulonglong2*)(g_xn + (size_t)n * HW_ * C_ + g * CG_) + cq;
        const float4* wv4 = w4s + g * P_ * 32;
        const int*    wvi = wis + g * P_ * 32;
        int wl = lane & 15;
        int ch = lane >> 4;

        #pragma unroll
        for (int half = 0; half < 2; half++) {
            #pragma unroll 2
            for (int q = 0; q < 4; q++) {
                int pixl = q * 4 + pixsub;            // 0..15 within half
                int pix = half * 16 + pixl;
                ull a0 = 0, a1 = 0;
                #pragma unroll
                for (int p = 0; p < P_; p++) {
                    float4 wv = wv4[p * 32 + pix];
                    int v = wvi[p * 32 + pix];
                    int base = (v & 0xFFF) << 6;      // off * 64 ulonglong2
                    int a = (v & 0x1000) >> 6;        // dx * 64
                    int b = (v & 0x2000) >> 1;        // dy * 4096
                    const ulonglong2* rp = xb + base;
                    ulonglong2 v00 = __ldg(rp);
                    ulonglong2 v01 = __ldg(rp + a);
                    ulonglong2 v10 = __ldg(rp + b);
                    ulonglong2 v11 = __ldg(rp + b + a);
                    ull w;
                    w = dup2(wv.x); fma2(a0, w, v00.x); fma2(a1, w, v00.y);
                    w = dup2(wv.y); fma2(a0, w, v01.x); fma2(a1, w, v01.y);
                    w = dup2(wv.z); fma2(a0, w, v10.x); fma2(a1, w, v10.y);
                    w = dup2(wv.w); fma2(a0, w, v11.x); fma2(a1, w, v11.y);
                }
                float2 f0 = unpack2(a0);
                float2 f1 = unpack2(a1);
                int c = g * CG_ + 4 * cq;
                float* ob = Obuf + pixl * 257 + c;
                ob[0] = f0.x; ob[1] = f0.y; ob[2] = f1.x; ob[3] = f1.y;
            }
            __syncwarp();

            // coalesced NCHW store of this half: 16 w x 2 c per iter
            #pragma unroll
            for (int i = 0; i < 16; i++) {
                int c = wid * 32 + 2 * i + ch;
                out[((size_t)(n * C_ + c) * H_ + h) * W_ + w0 + half * 16 + wl] =
                    Obuf[wl * 257 + c];
            }
            __syncwarp();
        }
    }
}

// ---------------------------------------------------------------------------
extern "C" void kernel_launch(void* const* d_in, const int* in_sizes, int n_in,
                              void* d_out, int out_size) {
    const float* x     = (const float*)d_in[0];
    const float* dw_w  = (const float*)d_in[1];
    const float* dw_b  = (const float*)d_in[2];
    const float* gn_g  = (const float*)d_in[3];
    const float* gn_b  = (const float*)d_in[4];
    const float* off_w = (const float*)d_in[5];
    const float* off_b = (const float*)d_in[6];
    const float* mask_w= (const float*)d_in[7];
    const float* mask_b= (const float*)d_in[8];
    float* out = (float*)d_out;

    cudaFuncSetAttribute(k_main, cudaFuncAttributeMaxDynamicSharedMemorySize, SMEM_MAIN);

    dim3 g1(W_ / 32, C_ / 32, NB * H_);
    dim3 b1(32, 8);
    k_conv<<<g1, b1>>>(x, dw_w, dw_b);
    k_stats<<<NB, 256>>>();
    dim3 g3(W_ / 32, H_, NB);
    k_main<<<g3, 256, SMEM_MAIN>>>(gn_g, gn_b, off_w, off_b, mask_w, mask_b, out);
}

// round 15
// speedup vs baseline: 1.5811x; 1.5811x over previous
#include <cuda_runtime.h>
#include <math.h>

#define NB 4
#define C_ 256
#define H_ 64
#define W_ 64
#define G_ 8
#define CG_ 32
#define P_ 9
#define HW_ (H_*W_)
#define M_ (C_*H_*W_)

// scratch (device globals; no allocation allowed)
__device__ float g_x1[NB*HW_*C_];          // NHWC conv+bias result
__device__ float g_xn[NB*HW_*C_];          // NHWC original x
__device__ float g_part[NB*1024*2];        // per-block partial sums
__device__ float g_ms[NB*2];               // per-sample mean, rstd

// fast exact-enough GELU: tanh-form with MUFU.TANH
__device__ __forceinline__ float gelu_fast(float v) {
    float u = 0.7978845608028654f * v * fmaf(0.044715f, v * v, 1.0f);
    float t;
    asm("tanh.approx.f32 %0, %1;" : "=f"(t) : "f"(u));
    return 0.5f * v * (1.0f + t);
}

// ---- f32x2 packed helpers (FFMA2 — only reachable via PTX) ----
typedef unsigned long long ull;
__device__ __forceinline__ ull dup2(float v) {
    ull r; asm("mov.b64 %0, {%1, %1};" : "=l"(r) : "f"(v)); return r;
}
__device__ __forceinline__ void fma2(ull& d, ull a, ull b) {
    asm("fma.rn.f32x2 %0, %1, %2, %0;" : "+l"(d) : "l"(a), "l"(b));
}
__device__ __forceinline__ float2 unpack2(ull v) {
    float2 f; asm("mov.b64 {%0, %1}, %2;" : "=f"(f.x), "=f"(f.y) : "l"(v)); return f;
}

// ---------------------------------------------------------------------------
// K1: depthwise 3x3 conv (+bias) NCHW -> NHWC, transpose x -> NHWC,
//     per-block partial GroupNorm sums. (R12-proven version.)
// grid: (W/32, C/32, N*H), block: (32, 8)
// ---------------------------------------------------------------------------
__global__ __launch_bounds__(256) void k_conv(const float* __restrict__ x,
                                              const float* __restrict__ dww,
                                              const float* __restrict__ dwb) {
    int wt = blockIdx.x, ct = blockIdx.y, nh = blockIdx.z;
    int n = nh >> 6, h = nh & 63;
    int w = wt * 32 + threadIdx.x;
    int c0 = ct * 32;

    __shared__ float t1[32][33];
    __shared__ float t0[32][33];
    __shared__ float rs8[8], rq8[8];

    float s1 = 0.f, s2 = 0.f;

    #pragma unroll
    for (int i = 0; i < 4; i++) {
        int cl = threadIdx.y * 4 + i;
        int c = c0 + cl;
        const float* xp = x + ((size_t)(n * C_ + c) * H_) * W_;
        float wgt[9];
        #pragma unroll
        for (int k = 0; k < 9; k++) wgt[k] = dww[c * 9 + k];
        float acc = dwb[c];
        float center = 0.f;
        #pragma unroll
        for (int dy = 0; dy < 3; dy++) {
            int hy = h + dy - 1;
            if (hy < 0 || hy >= H_) continue;
            #pragma unroll
            for (int dx = 0; dx < 3; dx++) {
                int wx = w + dx - 1;
                if (wx < 0 || wx >= W_) continue;
                float v = __ldg(xp + hy * W_ + wx);
                acc = fmaf(wgt[dy * 3 + dx], v, acc);
                if (dy == 1 && dx == 1) center = v;
            }
        }
        t1[cl][threadIdx.x] = acc;
        t0[cl][threadIdx.x] = center;
        s1 += acc;
        s2 += acc * acc;
    }

    #pragma unroll
    for (int o = 16; o; o >>= 1) {
        s1 += __shfl_xor_sync(0xFFFFFFFFu, s1, o);
        s2 += __shfl_xor_sync(0xFFFFFFFFu, s2, o);
    }
    if (threadIdx.x == 0) { rs8[threadIdx.y] = s1; rq8[threadIdx.y] = s2; }
    __syncthreads();
    if (threadIdx.x == 0 && threadIdx.y == 0) {
        float a = 0.f, b = 0.f;
        #pragma unroll
        for (int i = 0; i < 8; i++) { a += rs8[i]; b += rq8[i]; }
        int pid = (h * 2 + wt) * 8 + ct;
        g_part[(n * 1024 + pid) * 2 + 0] = a;
        g_part[(n * 1024 + pid) * 2 + 1] = b;
    }

    #pragma unroll
    for (int i = 0; i < 4; i++) {
        int ww = threadIdx.y + 8 * i;
        size_t pix = (size_t)(n * H_ + h) * W_ + wt * 32 + ww;
        g_x1[pix * C_ + c0 + threadIdx.x] = t1[threadIdx.x][ww];
        g_xn[pix * C_ + c0 + threadIdx.x] = t0[threadIdx.x][ww];
    }
}

// ---------------------------------------------------------------------------
// K2: finalize per-sample mean / rstd
// ---------------------------------------------------------------------------
__global__ void k_stats() {
    int n = blockIdx.x;
    int t = threadIdx.x;
    float s1 = 0.f, s2 = 0.f;
    for (int i = t; i < 1024; i += 256) {
        s1 += g_part[(n * 1024 + i) * 2 + 0];
        s2 += g_part[(n * 1024 + i) * 2 + 1];
    }
    __shared__ float rs[256];
    __shared__ float rq[256];
    rs[t] = s1; rq[t] = s2;
    __syncthreads();
    #pragma unroll
    for (int s = 128; s > 0; s >>= 1) {
        if (t < s) { rs[t] += rs[t + s]; rq[t] += rq[t + s]; }
        __syncthreads();
    }
    if (t == 0) {
        float mu = rs[0] / (float)M_;
        float var = rq[0] / (float)M_ - mu * mu;
        g_ms[n * 2 + 0] = mu;
        g_ms[n * 2 + 1] = rsqrtf(var + 1e-5f);
    }
}

// ---------------------------------------------------------------------------
// K3 (merged): GN + GELU + projection GEMM (FFMA2, pixel-packed) + softmax +
// weight precompute (to SMEM) + quad-pixel LDG.128 gather + coalesced store.
// smem layout (words):
//   [0,     9216)  Ys[256][36]  -> reused as w4 float4[72][32]
//   [9216, 16344)  O[216][33]   -> reused as Obuf[16][257] per half
//   [16344,18648)  wi int[72][32]
// 74.6KB -> 3 blocks/SM. grid (2,64,4), block 256.
// Gather/store phase uses only intra-warp data -> __syncwarp, warps drift.
// ---------------------------------------------------------------------------
#define YS_W   9216
#define O_W    7128
#define WI_W   2304
#define SMEM_MAIN ((YS_W + O_W + WI_W) * 4)

__global__ __launch_bounds__(256, 3) void k_main(const float* __restrict__ gng,
                                                 const float* __restrict__ gnb,
                                                 const float* __restrict__ offw,
                                                 const float* __restrict__ offb,
                                                 const float* __restrict__ maskw,
                                                 const float* __restrict__ maskb,
                                                 float* __restrict__ out) {
    extern __shared__ __align__(16) float sm[];
    float*  Ys   = sm;                         // [256][36]
    float*  O    = sm + YS_W;                  // [216][33]
    float4* w4s  = (float4*)sm;                // [72][32] float4 (overlays Ys)
    int*    wis  = (int*)(sm + YS_W + O_W);    // [72][32]
    float*  Obuf = sm + YS_W;                  // [16][257]  (overlays O)

    int wt = blockIdx.x, h = blockIdx.y, n = blockIdx.z;
    int w0 = wt * 32;
    int t = threadIdx.x;
    int lane = t & 31;
    int wid = t >> 5;

    float mu = g_ms[n * 2 + 0];
    float rstd = g_ms[n * 2 + 1];

    // ---- Phase A: GN + GELU into Ys[c][pix] ----
    size_t pixbase = (size_t)(n * H_ + h) * W_ + w0;
    #pragma unroll
    for (int q = 0; q < 4; q++) {
        int pix = wid * 4 + q;
        const float* src = g_x1 + (pixbase + pix) * C_;
        #pragma unroll
        for (int half = 0; half < 2; half++) {
            int c = lane * 4 + half * 128;
            float4 v  = *(const float4*)(src + c);
            float4 gg = *(const float4*)(gng + c);
            float4 bb = *(const float4*)(gnb + c);
            Ys[(c + 0) * 36 + pix] = gelu_fast(fmaf((v.x - mu) * rstd, gg.x, bb.x));
            Ys[(c + 1) * 36 + pix] = gelu_fast(fmaf((v.y - mu) * rstd, gg.y, bb.y));
            Ys[(c + 2) * 36 + pix] = gelu_fast(fmaf((v.z - mu) * rstd, gg.z, bb.z));
            Ys[(c + 3) * 36 + pix] = gelu_fast(fmaf((v.w - mu) * rstd, gg.w, bb.w));
        }
    }
    __syncthreads();

    // ---- Phase B: GEMM O[216][32] = W^T @ Ys + bias (f32x2 pixel pairs) ----
    if (t < 216) {
        int jt = t >> 2, pt = t & 3;
        int j0 = jt * 4;
        const float* wb;
        const float* bptr;
        int stride;
        if (j0 < 144) { wb = offw + j0; bptr = offb + j0; stride = 144; }
        else          { wb = maskw + (j0 - 144); bptr = maskb + (j0 - 144); stride = 72; }

        ull acc[16];   // [jj][pixpair]
        #pragma unroll
        for (int jj = 0; jj < 4; jj++) {
            ull b = dup2(bptr[jj]);
            #pragma unroll
            for (int pp = 0; pp < 4; pp++) acc[jj * 4 + pp] = b;
        }

        const ull* yc = (const ull*)(Ys + pt * 8);
        #pragma unroll 2
        for (int c = 0; c < 256; c++) {
            float4 wv = *(const float4*)(wb + (size_t)c * stride);
            ull wd[4];
            wd[0] = dup2(wv.x); wd[1] = dup2(wv.y); wd[2] = dup2(wv.z); wd[3] = dup2(wv.w);
            ull y0 = yc[0], y1 = yc[1], y2 = yc[2], y3 = yc[3];
            #pragma unroll
            for (int jj = 0; jj < 4; jj++) {
                fma2(acc[jj * 4 + 0], wd[jj], y0);
                fma2(acc[jj * 4 + 1], wd[jj], y1);
                fma2(acc[jj * 4 + 2], wd[jj], y2);
                fma2(acc[jj * 4 + 3], wd[jj], y3);
            }
            yc += 18;   // 36 floats
        }

        #pragma unroll
        for (int jj = 0; jj < 4; jj++)
            #pragma unroll
            for (int pp = 0; pp < 4; pp++) {
                float2 f = unpack2(acc[jj * 4 + pp]);
                O[(j0 + jj) * 33 + pt * 8 + 2 * pp + 0] = f.x;
                O[(j0 + jj) * 33 + pt * 8 + 2 * pp + 1] = f.y;
            }
    }
    __syncthreads();

    // ---- Phase C1: softmax + premultiplied bilinear weights -> SMEM ----
    {
        int g = wid, pix = lane;
        float ml[9];
        float mx = -1e30f;
        #pragma unroll
        for (int p = 0; p < P_; p++) {
            ml[p] = O[(144 + g * P_ + p) * 33 + pix];
            mx = fmaxf(mx, ml[p]);
        }
        float s = 0.f;
        #pragma unroll
        for (int p = 0; p < P_; p++) { ml[p] = __expf(ml[p] - mx); s += ml[p]; }
        float inv = 1.f / s;

        float wpixf = (float)(w0 + pix);
        float hf = (float)h;
        #pragma unroll
        for (int p = 0; p < P_; p++) {
            float ox = O[((g * P_ + p) * 2 + 0) * 33 + pix];
            float oy = O[((g * P_ + p) * 2 + 1) * 33 + pix];
            float fx = wpixf + (float)(p / 3 - 1) + ox;
            float fy = hf    + (float)(p % 3 - 1) + oy;
            fx = fminf(fmaxf(fx, -2.f), (float)(W_ + 1));
            fy = fminf(fmaxf(fy, -2.f), (float)(H_ + 1));
            float x0f = floorf(fx), y0f = floorf(fy);
            float wxf = fx - x0f, wyf = fy - y0f;
            int ix = (int)x0f, iy = (int)y0f;
            float m = ml[p] * inv;
            float ax0 = (ix >= 0 && ix < W_)          ? (1.f - wxf) : 0.f;
            float ax1 = (ix + 1 >= 0 && ix + 1 < W_)  ? wxf         : 0.f;
            float ay0 = (iy >= 0 && iy < H_)          ? (1.f - wyf) : 0.f;
            float ay1 = (iy + 1 >= 0 && iy + 1 < H_)  ? wyf         : 0.f;
            float4 wv;
            wv.x = m * ay0 * ax0;
            wv.y = m * ay0 * ax1;
            wv.z = m * ay1 * ax0;
            wv.w = m * ay1 * ax1;
            int ix0c = min(max(ix, 0), W_ - 1);
            int iy0c = min(max(iy, 0), H_ - 1);
            int dx   = min(max(ix + 1, 0), W_ - 1) - ix0c;
            int dy   = min(max(iy + 1, 0), H_ - 1) - iy0c;
            int off  = iy0c * W_ + ix0c;
            int idx = (g * P_ + p) * 32 + pix;
            w4s[idx] = wv;
            wis[idx] = off | (dx << 12) | (dy << 13);
        }
    }
    __syncthreads();   // Obuf overlays O; all warps' C1 reads of O must finish

    // ---- Phase C2+D: quad-pixel LDG.128 gather, two 16-pixel halves ----
    // All smem traffic below is intra-warp (warp g owns channels g*32..+31,
    // its own w4s/wis records, its own Obuf columns) -> __syncwarp only.
    {
        int g = wid;
        int pixsub = lane >> 3;
        int cq = lane & 7;
        const ulonglong2* xb =
            (const ulonglong2*)(g_xn + (size_t)n * HW_ * C_ + g * CG_) + cq;
        const float4* wv4 = w4s + g * P_ * 32;
        const int*    wvi = wis + g * P_ * 32;
        int wl = lane & 15;
        int ch = lane >> 4;

        #pragma unroll
        for (int half = 0; half < 2; half++) {
            #pragma unroll 2
            for (int q = 0; q < 4; q++) {
                int pixl = q * 4 + pixsub;            // 0..15 within half
                int pix = half * 16 + pixl;
                ull a0 = 0, a1 = 0;
                #pragma unroll
                for (int p = 0; p < P_; p++) {
                    float4 wv = wv4[p * 32 + pix];
                    int v = wvi[p * 32 + pix];
                    int base = (v & 0xFFF) << 6;      // off * 64 ulonglong2
                    int a = (v & 0x1000) >> 6;        // dx * 64
                    int b = (v & 0x2000) >> 1;        // dy * 4096
                    const ulonglong2* rp = xb + base;
                    ulonglong2 v00 = __ldg(rp);
                    ulonglong2 v01 = __ldg(rp + a);
                    ulonglong2 v10 = __ldg(rp + b);
                    ulonglong2 v11 = __ldg(rp + b + a);
                    ull w;
                    w = dup2(wv.x); fma2(a0, w, v00.x); fma2(a1, w, v00.y);
                    w = dup2(wv.y); fma2(a0, w, v01.x); fma2(a1, w, v01.y);
                    w = dup2(wv.z); fma2(a0, w, v10.x); fma2(a1, w, v10.y);
                    w = dup2(wv.w); fma2(a0, w, v11.x); fma2(a1, w, v11.y);
                }
                float2 f0 = unpack2(a0);
                float2 f1 = unpack2(a1);
                int c = g * CG_ + 4 * cq;
                float* ob = Obuf + pixl * 257 + c;
                ob[0] = f0.x; ob[1] = f0.y; ob[2] = f1.x; ob[3] = f1.y;
            }
            __syncwarp();

            // coalesced NCHW store of this half: 16 w x 2 c per iter
            #pragma unroll
            for (int i = 0; i < 16; i++) {
                int c = wid * 32 + 2 * i + ch;
                out[((size_t)(n * C_ + c) * H_ + h) * W_ + w0 + half * 16 + wl] =
                    Obuf[wl * 257 + c];
            }
            __syncwarp();
        }
    }
}

// ---------------------------------------------------------------------------
extern "C" void kernel_launch(void* const* d_in, const int* in_sizes, int n_in,
                              void* d_out, int out_size) {
    const float* x     = (const float*)d_in[0];
    const float* dw_w  = (const float*)d_in[1];
    const float* dw_b  = (const float*)d_in[2];
    const float* gn_g  = (const float*)d_in[3];
    const float* gn_b  = (const float*)d_in[4];
    const float* off_w = (const float*)d_in[5];
    const float* off_b = (const float*)d_in[6];
    const float* mask_w= (const float*)d_in[7];
    const float* mask_b= (const float*)d_in[8];
    float* out = (float*)d_out;

    cudaFuncSetAttribute(k_main, cudaFuncAttributeMaxDynamicSharedMemorySize, SMEM_MAIN);

    dim3 g1(W_ / 32, C_ / 32, NB * H_);
    dim3 b1(32, 8);
    k_conv<<<g1, b1>>>(x, dw_w, dw_b);
    k_stats<<<NB, 256>>>();
    dim3 g3(W_ / 32, H_, NB);
    k_main<<<g3, 256, SMEM_MAIN>>>(gn_g, gn_b, off_w, off_b, mask_w, mask_b, out);
}